// round 17
// baseline (speedup 1.0000x reference)
#include <cuda_runtime.h>
#include <math.h>

// Problem constants
#define BB   8
#define NN   20000
#define NPAD 20480        // 160 * 128
#define QTR  (NPAD/4)
#define PP   256
#define SS   32
#define CC   256
#define NCC  18
#define BP   (BB*PP)      // 2048
#define HST2 36           // channel-major hidden row stride (32 pts + 4 pad)

typedef unsigned long long ull;

// packed f32x2 helpers (sm_103a)
#define FMA_F32X2(a, x, w) \
    asm("fma.rn.f32x2 %0, %1, %2, %0;" : "+l"(a) : "l"(x), "l"(w))
__device__ __forceinline__ ull pack2(float v) {
    ull r; asm("mov.b64 %0, {%1, %1};" : "=l"(r) : "f"(v)); return r;
}
__device__ __forceinline__ float2 unpack2(ull a) {
    float2 f; asm("mov.b64 {%0, %1}, %2;" : "=f"(f.x), "=f"(f.y) : "l"(a)); return f;
}

// ---------------- scratch (__device__ globals; no allocation allowed) ---------------
// NOTE: never pass these as kernel arguments from host code (ATS hides the bug).
__device__ int   g_sel[BP*SS];
__device__ float g_nf [BP*128];
__device__ float g_lf [BP*256];
__device__ float g_ss [BB*256];
__device__ float g_ss2[BB*512];
__device__ __align__(16) float g_sx[BB*NPAD];
__device__ __align__(16) float g_sy[BB*NPAD];
__device__ __align__(16) float g_sz[BB*NPAD];
__device__ __align__(16) float g_ft[(size_t)BB*NN*CC];   // features transposed [b][n][c]

// transposed weights [K][O]; g_mw0t rows permuted: c<256 = feature c, 256..258 = xyz
__device__ __align__(16) float g_mw0t [259*128];
__device__ __align__(16) float g_mw1t [128*128];
__device__ __align__(16) float g_mw2t [128*128];
__device__ __align__(16) float g_lw0t [146*256];
__device__ __align__(16) float g_lw1t [256*256];
__device__ __align__(16) float g_lw2t [256*256];

__device__ __forceinline__ float gelu_exact(float x) {
    return 0.5f * x * (1.0f + erff(x * 0.70710678118654752f));
}
__device__ __forceinline__ float silu_f(float x) { return x / (1.0f + expf(-x)); }
__device__ __forceinline__ float relu_f(float x) { return fmaxf(x, 0.0f); }

// ---------------- kernel P: fused prep = xyz SoA + 6 weight transposes --------------
__global__ void k_prep(const float* __restrict__ xyz,
                       const float* __restrict__ mw0, const float* __restrict__ mw1,
                       const float* __restrict__ mw2, const float* __restrict__ lw0,
                       const float* __restrict__ lw1, const float* __restrict__ lw2) {
    int blk = blockIdx.x;
    int tx = threadIdx.x, ty = threadIdx.y;
    int tid = ty * 32 + tx;
    if (blk < 640) {
        int i = blk * 256 + tid;
        if (i >= BB * NPAD) return;
        int b = i / NPAD, n = i - b * NPAD;
        float x = 3e38f, y = 3e38f, z = 3e38f;
        if (n < NN) {
            const float* p = xyz + ((size_t)b * NN + n) * 3;
            x = p[0]; y = p[1]; z = p[2];
        }
        g_sx[i] = x; g_sy[i] = y; g_sz[i] = z;
        return;
    }
    int t = blk - 640;
    const float* src; float* dst; int O, K, base; bool perm = false;
    if      (t < 36)  { src = mw0; dst = g_mw0t; O = 128; K = 259; base = 0;   perm = true; }
    else if (t < 52)  { src = mw1; dst = g_mw1t; O = 128; K = 128; base = 36;  }
    else if (t < 68)  { src = mw2; dst = g_mw2t; O = 128; K = 128; base = 52;  }
    else if (t < 108) { src = lw0; dst = g_lw0t; O = 256; K = 146; base = 68;  }
    else if (t < 172) { src = lw1; dst = g_lw1t; O = 256; K = 256; base = 108; }
    else              { src = lw2; dst = g_lw2t; O = 256; K = 256; base = 172; }
    int tile = t - base;
    int ntk = (K + 31) >> 5;
    int kt = tile % ntk, ot = tile / ntk;
    __shared__ float s[32][33];
    int k0 = kt * 32, o0 = ot * 32;
    #pragma unroll
    for (int i = ty; i < 32; i += 8) {
        int o = o0 + i, k = k0 + tx;
        if (o < O && k < K) {
            int sk = perm ? (k < 256 ? k + 3 : k - 256) : k;
            s[i][tx] = src[o * K + sk];
        }
    }
    __syncthreads();
    #pragma unroll
    for (int i = ty; i < 32; i += 8) {
        int k = k0 + i, o = o0 + tx;
        if (k < K && o < O) dst[k * O + o] = s[tx][i];
    }
}

// ---------------- kernel F: feature transpose [C][N] -> [N][C] ----------------------
__global__ void k_ftrans(const float* __restrict__ feat) {
    __shared__ float t[32][33];
    int tx = threadIdx.x, ty = threadIdx.y;
    int n0 = blockIdx.x << 5, c0 = blockIdx.y << 5, b = blockIdx.z;
    const float* src = feat + ((size_t)(b * CC + c0)) * NN + n0;
    #pragma unroll
    for (int i = ty; i < 32; i += 8)
        t[i][tx] = src[(size_t)i * NN + tx];
    __syncthreads();
    float* dst = g_ft + ((size_t)b * NN + n0) * CC + c0;
    #pragma unroll
    for (int i = ty; i < 32; i += 8)
        dst[(size_t)i * CC + tx] = t[tx][i];
}

// ---------------- kernel A: in-box sampling, 4 warps/proposal quarter-scan + merge --
__global__ void __launch_bounds__(128) k_sample(const float* __restrict__ xyz,
                         const float* __restrict__ bsize,
                         const int*   __restrict__ inds) {
    __shared__ int buf[4][SS];
    __shared__ int cnt[4];
    int tid = threadIdx.x;
    int lane = tid & 31, w = tid >> 5;
    int q = blockIdx.x;
    int b = q >> 8;
    int n0 = inds[q];
    const float* cp = xyz + ((size_t)b * NN + n0) * 3;
    float cx = cp[0], cy = cp[1], cz = cp[2];
    float hx = bsize[q*3+0]*0.5f, hy = bsize[q*3+1]*0.5f, hz = bsize[q*3+2]*0.5f;
    const float4* X = (const float4*)(g_sx + b * NPAD);
    const float4* Y = (const float4*)(g_sy + b * NPAD);
    const float4* Z = (const float4*)(g_sz + b * NPAD);

    int vbase = w * (QTR/4);
    unsigned below = (1u << lane) - 1u;
    int found = 0;
    float4 xs = X[vbase + lane], ys = Y[vbase + lane], zs = Z[vbase + lane];
    const int ITERS = QTR / 128;                   // 40
    for (int it = 0; it < ITERS; it++) {
        float4 nx, ny, nz;
        if (it + 1 < ITERS) {
            int v = vbase + (it + 1) * 32 + lane;
            nx = X[v]; ny = Y[v]; nz = Z[v];
        }
        bool i0 = (fabsf(xs.x-cx)<=hx) && (fabsf(ys.x-cy)<=hy) && (fabsf(zs.x-cz)<=hz);
        bool i1 = (fabsf(xs.y-cx)<=hx) && (fabsf(ys.y-cy)<=hy) && (fabsf(zs.y-cz)<=hz);
        bool i2 = (fabsf(xs.z-cx)<=hx) && (fabsf(ys.z-cy)<=hy) && (fabsf(zs.z-cz)<=hz);
        bool i3 = (fabsf(xs.w-cx)<=hx) && (fabsf(ys.w-cy)<=hy) && (fabsf(zs.w-cz)<=hz);
        unsigned m0 = __ballot_sync(0xffffffffu, i0);
        unsigned m1 = __ballot_sync(0xffffffffu, i1);
        unsigned m2 = __ballot_sync(0xffffffffu, i2);
        unsigned m3 = __ballot_sync(0xffffffffu, i3);
        if (m0 | m1 | m2 | m3) {
            int pre = found
                    + __popc(m0 & below) + __popc(m1 & below)
                    + __popc(m2 & below) + __popc(m3 & below);
            int np = w * QTR + it * 128 + 4 * lane;
            unsigned b0 = (m0 >> lane) & 1u, b1 = (m1 >> lane) & 1u, b2 = (m2 >> lane) & 1u;
            if (i0 && pre < SS)                    buf[w][pre] = np;
            int r1 = pre + (int)b0;
            if (i1 && r1 < SS)                     buf[w][r1] = np + 1;
            int r2 = r1 + (int)b1;
            if (i2 && r2 < SS)                     buf[w][r2] = np + 2;
            int r3 = r2 + (int)b2;
            if (i3 && r3 < SS)                     buf[w][r3] = np + 3;
        }
        found += __popc(m0) + __popc(m1) + __popc(m2) + __popc(m3);
        if (found >= SS) break;
        xs = nx; ys = ny; zs = nz;
    }
    if (lane == 0) cnt[w] = found;
    __syncthreads();

    if (tid < 32) {
        int c0 = cnt[0], c1 = cnt[1], c2 = cnt[2], c3 = cnt[3];
        int s0 = c0 < SS ? c0 : SS;
        int s1 = c1 < SS ? c1 : SS;
        int s2 = c2 < SS ? c2 : SS;
        int total = c0 + c1 + c2 + c3;
        int eff = total < SS ? total : SS;
        int sel = 0;
        if (eff > 0) {
            int j = tid % eff;
            if (j < s0) sel = buf[0][j];
            else { j -= s0;
                if (j < s1) sel = buf[1][j];
                else { j -= s1;
                    if (j < s2) sel = buf[2][j];
                    else sel = buf[3][j - s2];
                }
            }
        }
        g_sel[q*SS + tid] = sel;
    }
}

// ---------------- kernel E: FUSED time-MLP chain (1 block per batch) ----------------
__device__ __forceinline__ float warp_dot4(const float* __restrict__ w,
                                           const float* __restrict__ in, int K, int lane) {
    float a = 0.0f;
    for (int c = 4*lane; c < K; c += 128) {
        float4 wv = *(const float4*)(w + c);
        float4 iv = *(const float4*)(in + c);
        a += wv.x*iv.x + wv.y*iv.y + wv.z*iv.z + wv.w*iv.w;
    }
    a += __shfl_xor_sync(0xffffffffu, a, 16);
    a += __shfl_xor_sync(0xffffffffu, a, 8);
    a += __shfl_xor_sync(0xffffffffu, a, 4);
    a += __shfl_xor_sync(0xffffffffu, a, 2);
    a += __shfl_xor_sync(0xffffffffu, a, 1);
    return a;
}

__global__ void __launch_bounds__(1024) k_time2(const float* __restrict__ ts,
                       const float* __restrict__ tw0, const float* __restrict__ tb0,
                       const float* __restrict__ tw1, const float* __restrict__ tb1,
                       const float* __restrict__ bw,  const float* __restrict__ bb_,
                       const float* __restrict__ tlw0, const float* __restrict__ tlb0,
                       const float* __restrict__ tlw1, const float* __restrict__ tlb1,
                       const float* __restrict__ blw,  const float* __restrict__ blb) {
    __shared__ __align__(16) float e1[128], e2[256], t1[512], s1[512], t2[1024], s2[1024];
    int b = blockIdx.x, tid = threadIdx.x;           // 1024 threads
    int lane = tid & 31, warp = tid >> 5;            // 32 warps
    float t = ts[b];
    if (tid < 64)  { float f = expf(tid * (-9.210340371976184f/63.0f));
                     float e = t*f; e1[tid] = sinf(e); e1[64+tid]  = cosf(e); }
    if (tid < 128) { float f = expf(tid * (-9.210340371976184f/127.0f));
                     float e = t*f; e2[tid] = sinf(e); e2[128+tid] = cosf(e); }
    __syncthreads();
    for (int r = warp; r < 512; r += 32) {
        float a = warp_dot4(tw0 + r*128, e1, 128, lane) + tb0[r];
        if (lane == 0) t1[r] = gelu_exact(a);
    }
    for (int r = warp; r < 1024; r += 32) {
        float a = warp_dot4(tlw0 + r*256, e2, 256, lane) + tlb0[r];
        if (lane == 0) t2[r] = gelu_exact(a);
    }
    __syncthreads();
    for (int r = warp; r < 512; r += 32) {
        float a = warp_dot4(tw1 + r*512, t1, 512, lane) + tb1[r];
        if (lane == 0) s1[r] = silu_f(a);
    }
    for (int r = warp; r < 1024; r += 32) {
        float a = warp_dot4(tlw1 + (size_t)r*1024, t2, 1024, lane) + tlb1[r];
        if (lane == 0) s2[r] = silu_f(a);
    }
    __syncthreads();
    for (int r = warp; r < 256; r += 32) {
        float a = warp_dot4(bw + r*512, s1, 512, lane) + bb_[r];
        if (lane == 0) g_ss[b*256 + r] = a;
    }
    for (int r = warp; r < 512; r += 32) {
        float a = warp_dot4(blw + (size_t)r*1024, s2, 1024, lane) + blb[r];
        if (lane == 0) g_ss2[b*512 + r] = a;
    }
}

// ---------------- kernel B: point MLP; layer0 streams x straight from g_ft ----------
// Block = 1 proposal; 128 threads; thread = 4 pts x 8 outs (16 b64 f32x2 accs).
// smem = 2 x [128][HST2] hidden buffers only (36.9KB) -> 5 blocks/SM.

// layers 1/2: channel-major input [128][HST2]; pg in [0,8), ohh in [0,16)
__device__ __forceinline__ void layerN4(const float* __restrict__ in,
                                        const float* __restrict__ wt,   // [128][128]
                                        const float* __restrict__ bias,
                                        float* __restrict__ out,        // [128][HST2]
                                        int pg, int ohh) {
    ull acc[4][4];
    {
        const ull* bp = (const ull*)(bias + 8*ohh);
        ull b0 = bp[0], b1 = bp[1], b2 = bp[2], b3 = bp[3];
        #pragma unroll
        for (int j = 0; j < 4; j++) {
            acc[j][0] = b0; acc[j][1] = b1; acc[j][2] = b2; acc[j][3] = b3;
        }
    }
    const float* ip = in + 4*pg;
    const float* wp = wt + 8*ohh;
    #pragma unroll 4
    for (int c = 0; c < 128; c++) {
        float4 x = *(const float4*)(ip + c*HST2);
        ull x0 = pack2(x.x), x1 = pack2(x.y), x2 = pack2(x.z), x3 = pack2(x.w);
        ulonglong2 wa = *(const ulonglong2*)(wp + c*128);
        ulonglong2 wb = *(const ulonglong2*)(wp + c*128 + 4);
        FMA_F32X2(acc[0][0], x0, wa.x); FMA_F32X2(acc[1][0], x1, wa.x);
        FMA_F32X2(acc[2][0], x2, wa.x); FMA_F32X2(acc[3][0], x3, wa.x);
        FMA_F32X2(acc[0][1], x0, wa.y); FMA_F32X2(acc[1][1], x1, wa.y);
        FMA_F32X2(acc[2][1], x2, wa.y); FMA_F32X2(acc[3][1], x3, wa.y);
        FMA_F32X2(acc[0][2], x0, wb.x); FMA_F32X2(acc[1][2], x1, wb.x);
        FMA_F32X2(acc[2][2], x2, wb.x); FMA_F32X2(acc[3][2], x3, wb.x);
        FMA_F32X2(acc[0][3], x0, wb.y); FMA_F32X2(acc[1][3], x1, wb.y);
        FMA_F32X2(acc[2][3], x2, wb.y); FMA_F32X2(acc[3][3], x3, wb.y);
    }
    #pragma unroll
    for (int k = 0; k < 4; k++) {
        float2 f0 = unpack2(acc[0][k]);
        float2 f1 = unpack2(acc[1][k]);
        float2 f2 = unpack2(acc[2][k]);
        float2 f3 = unpack2(acc[3][k]);
        *(float4*)(out + (8*ohh + 2*k)*HST2 + 4*pg) =
            make_float4(relu_f(f0.x), relu_f(f1.x), relu_f(f2.x), relu_f(f3.x));
        *(float4*)(out + (8*ohh + 2*k + 1)*HST2 + 4*pg) =
            make_float4(relu_f(f0.y), relu_f(f1.y), relu_f(f2.y), relu_f(f3.y));
    }
}

__global__ void __launch_bounds__(128, 5) k_mlp(
                      const float* __restrict__ xyz,
                      const int* __restrict__ inds,
                      const float* __restrict__ mb0, const float* __restrict__ mb1,
                      const float* __restrict__ mb2) {
    extern __shared__ float sm[];
    float* hA = sm;                     // [128][HST2]
    float* hB = sm + 128*HST2;          // [128][HST2]
    __shared__ int   sidx[32];
    __shared__ float sxyz[3][33];

    int q = blockIdx.x, b = q >> 8;
    int tid = threadIdx.x;              // 128 threads
    if (tid < 32) sidx[tid] = g_sel[q*SS + tid];
    __syncthreads();
    if (tid < 32) {
        const float* p = xyz + ((size_t)b*NN + sidx[tid])*3;
        const float* cp = xyz + ((size_t)b*NN + inds[q])*3;
        #pragma unroll
        for (int d = 0; d < 3; d++) sxyz[d][tid] = p[d] - cp[d];
    }
    __syncthreads();

    int pg = tid & 7, ohh = tid >> 3;    // pg: 4-point group, ohh: 8-out group

    // ---- layer 0: x streamed from g_ft rows (L2/L1 resident), weights row-major ----
    {
        ull acc[4][4];
        {
            const ull* bp = (const ull*)(mb0 + 8*ohh);
            ull b0 = bp[0], b1 = bp[1], b2 = bp[2], b3 = bp[3];
            #pragma unroll
            for (int j = 0; j < 4; j++) {
                acc[j][0] = b0; acc[j][1] = b1; acc[j][2] = b2; acc[j][3] = b3;
            }
        }
        const float* ftb = g_ft + (size_t)b * NN * CC;
        const float* p0 = ftb + (size_t)sidx[4*pg + 0] * CC;
        const float* p1 = ftb + (size_t)sidx[4*pg + 1] * CC;
        const float* p2 = ftb + (size_t)sidx[4*pg + 2] * CC;
        const float* p3 = ftb + (size_t)sidx[4*pg + 3] * CC;
        const float* wp = g_mw0t + 8*ohh;
        #pragma unroll 2
        for (int c = 0; c < 256; c += 4) {
            float4 q0 = *(const float4*)(p0 + c);
            float4 q1 = *(const float4*)(p1 + c);
            float4 q2 = *(const float4*)(p2 + c);
            float4 q3 = *(const float4*)(p3 + c);
            #pragma unroll
            for (int k = 0; k < 4; k++) {
                float xv0 = (&q0.x)[k], xv1 = (&q1.x)[k];
                float xv2 = (&q2.x)[k], xv3 = (&q3.x)[k];
                ull x0 = pack2(xv0), x1 = pack2(xv1);
                ull x2 = pack2(xv2), x3 = pack2(xv3);
                ulonglong2 wa = *(const ulonglong2*)(wp + (c+k)*128);
                ulonglong2 wb = *(const ulonglong2*)(wp + (c+k)*128 + 4);
                FMA_F32X2(acc[0][0], x0, wa.x); FMA_F32X2(acc[1][0], x1, wa.x);
                FMA_F32X2(acc[2][0], x2, wa.x); FMA_F32X2(acc[3][0], x3, wa.x);
                FMA_F32X2(acc[0][1], x0, wa.y); FMA_F32X2(acc[1][1], x1, wa.y);
                FMA_F32X2(acc[2][1], x2, wa.y); FMA_F32X2(acc[3][1], x3, wa.y);
                FMA_F32X2(acc[0][2], x0, wb.x); FMA_F32X2(acc[1][2], x1, wb.x);
                FMA_F32X2(acc[2][2], x2, wb.x); FMA_F32X2(acc[3][2], x3, wb.x);
                FMA_F32X2(acc[0][3], x0, wb.y); FMA_F32X2(acc[1][3], x1, wb.y);
                FMA_F32X2(acc[2][3], x2, wb.y); FMA_F32X2(acc[3][3], x3, wb.y);
            }
        }
        #pragma unroll
        for (int d = 0; d < 3; d++) {                 // xyz channels 256..258
            int c = 256 + d;
            ull x0 = pack2(sxyz[d][4*pg + 0]), x1 = pack2(sxyz[d][4*pg + 1]);
            ull x2 = pack2(sxyz[d][4*pg + 2]), x3 = pack2(sxyz[d][4*pg + 3]);
            ulonglong2 wa = *(const ulonglong2*)(wp + c*128);
            ulonglong2 wb = *(const ulonglong2*)(wp + c*128 + 4);
            FMA_F32X2(acc[0][0], x0, wa.x); FMA_F32X2(acc[1][0], x1, wa.x);
            FMA_F32X2(acc[2][0], x2, wa.x); FMA_F32X2(acc[3][0], x3, wa.x);
            FMA_F32X2(acc[0][1], x0, wa.y); FMA_F32X2(acc[1][1], x1, wa.y);
            FMA_F32X2(acc[2][1], x2, wa.y); FMA_F32X2(acc[3][1], x3, wa.y);
            FMA_F32X2(acc[0][2], x0, wb.x); FMA_F32X2(acc[1][2], x1, wb.x);
            FMA_F32X2(acc[2][2], x2, wb.x); FMA_F32X2(acc[3][2], x3, wb.x);
            FMA_F32X2(acc[0][3], x0, wb.y); FMA_F32X2(acc[1][3], x1, wb.y);
            FMA_F32X2(acc[2][3], x2, wb.y); FMA_F32X2(acc[3][3], x3, wb.y);
        }
        #pragma unroll
        for (int k = 0; k < 4; k++) {
            float2 f0 = unpack2(acc[0][k]);
            float2 f1 = unpack2(acc[1][k]);
            float2 f2 = unpack2(acc[2][k]);
            float2 f3 = unpack2(acc[3][k]);
            *(float4*)(hA + (8*ohh + 2*k)*HST2 + 4*pg) =
                make_float4(relu_f(f0.x), relu_f(f1.x), relu_f(f2.x), relu_f(f3.x));
            *(float4*)(hA + (8*ohh + 2*k + 1)*HST2 + 4*pg) =
                make_float4(relu_f(f0.y), relu_f(f1.y), relu_f(f2.y), relu_f(f3.y));
        }
    }
    __syncthreads();

    layerN4(hA, g_mw1t, mb1, hB, pg, ohh);   __syncthreads();
    layerN4(hB, g_mw2t, mb2, hA, pg, ohh);   __syncthreads();

    // maxpool over 32 samples (relu outputs >= 0); 128 threads = 128 channels
    {
        const float* r = hA + tid*HST2;
        float m = 0.0f;
        #pragma unroll
        for (int j = 0; j < 32; j += 4) {
            float4 v = *(const float4*)(r + j);
            m = fmaxf(m, fmaxf(fmaxf(v.x, v.y), fmaxf(v.z, v.w)));
        }
        g_nf[q*128 + tid] = m;
    }
}

// ---------------- kernel C: label MLP, 4 proposals/block ----------------------------
__global__ void __launch_bounds__(256) k_label(const float* __restrict__ blabel,
                       const float* __restrict__ lb0, const float* __restrict__ lb1,
                       const float* __restrict__ lb2) {
    __shared__ float in0[4][152];
    __shared__ float h1[4][256];
    __shared__ float h2[4][256];
    int q0 = blockIdx.x * 4;
    int tid = threadIdx.x;               // 256 threads = 256 outputs
    if (tid < 4*NCC) {
        int j = tid / NCC, c = tid - j*NCC;
        in0[j][c] = blabel[(q0 + j)*NCC + c];
    }
    #pragma unroll
    for (int i = tid; i < 512; i += 256) {
        int j = i >> 7, c = i & 127;
        in0[j][NCC + c] = g_nf[(q0 + j)*128 + c];
    }
    __syncthreads();
    int o = tid;
    float a0 = lb0[o], a1 = a0, a2 = a0, a3 = a0;
    #pragma unroll 2
    for (int c = 0; c < 146; c++) {
        float w = g_lw0t[c*256 + o];
        a0 += in0[0][c]*w; a1 += in0[1][c]*w; a2 += in0[2][c]*w; a3 += in0[3][c]*w;
    }
    h1[0][o] = relu_f(a0); h1[1][o] = relu_f(a1);
    h1[2][o] = relu_f(a2); h1[3][o] = relu_f(a3);
    __syncthreads();
    a0 = lb1[o]; a1 = a0; a2 = a0; a3 = a0;
    #pragma unroll 4
    for (int c = 0; c < 256; c++) {
        float w = g_lw1t[c*256 + o];
        a0 += h1[0][c]*w; a1 += h1[1][c]*w; a2 += h1[2][c]*w; a3 += h1[3][c]*w;
    }
    h2[0][o] = relu_f(a0); h2[1][o] = relu_f(a1);
    h2[2][o] = relu_f(a2); h2[3][o] = relu_f(a3);
    __syncthreads();
    a0 = lb2[o]; a1 = a0; a2 = a0; a3 = a0;
    #pragma unroll 4
    for (int c = 0; c < 256; c++) {
        float w = g_lw2t[c*256 + o];
        a0 += h2[0][c]*w; a1 += h2[1][c]*w; a2 += h2[2][c]*w; a3 += h2[3][c]*w;
    }
    g_lf[(q0+0)*256 + o] = relu_f(a0);
    g_lf[(q0+1)*256 + o] = relu_f(a1);
    g_lf[(q0+2)*256 + o] = relu_f(a2);
    g_lf[(q0+3)*256 + o] = relu_f(a3);
}

// ---------------- kernel D: FiLM + all outputs ---------------------------------------
__global__ void k_out(float* __restrict__ out, const float* __restrict__ xyz,
                      const int* __restrict__ inds) {
    const int O0 = BB*PP*3;
    const int O1 = O0 + BB*128*PP;
    const int O2 = O1 + BB*256*PP;
    const int O3 = O2 + BB*PP;
    int i = blockIdx.x * blockDim.x + threadIdx.x;
    if (i < O0) {
        int b = i / (PP*3); int r = i - b*(PP*3); int p = r/3, d = r - p*3;
        out[i] = xyz[((size_t)b*NN + inds[b*PP + p])*3 + d];
    } else if (i < O1) {
        int j = i - O0;
        int b = j >> 15;
        int r = j & 32767;
        int d = r >> 8, p = r & 255;
        int m = p & 127;
        out[i] = g_nf[((b<<8) + p)*128 + d] * (g_ss[b*256 + m] + 1.0f)
               + g_ss[b*256 + 128 + m];
    } else if (i < O2) {
        int j = i - O1;
        int b = j >> 16;
        int r = j & 65535;
        int d = r >> 8, p = r & 255;
        out[i] = g_lf[((b<<8) + p)*256 + d] * (g_ss2[b*512 + p] + 1.0f)
               + g_ss2[b*512 + 256 + p];
    } else if (i < O3) {
        out[i] = (float)inds[i - O2];
    }
}

// ---------------- launcher -----------------------------------------------------------
extern "C" void kernel_launch(void* const* d_in, const int* in_sizes, int n_in,
                              void* d_out, int out_size) {
    const float* xyz    = (const float*)d_in[0];
    const float* feat   = (const float*)d_in[1];
    const float* bsize  = (const float*)d_in[2];
    const float* blabel = (const float*)d_in[3];
    const float* ts     = (const float*)d_in[4];
    const int*   inds   = (const int*)  d_in[5];
    const float* mw0 = (const float*)d_in[6],  *mb0 = (const float*)d_in[7];
    const float* mw1 = (const float*)d_in[8],  *mb1 = (const float*)d_in[9];
    const float* mw2 = (const float*)d_in[10], *mb2 = (const float*)d_in[11];
    const float* lw0 = (const float*)d_in[12], *lb0 = (const float*)d_in[13];
    const float* lw1 = (const float*)d_in[14], *lb1 = (const float*)d_in[15];
    const float* lw2 = (const float*)d_in[16], *lb2 = (const float*)d_in[17];
    const float* tw0 = (const float*)d_in[18], *tb0 = (const float*)d_in[19];
    const float* tw1 = (const float*)d_in[20], *tb1 = (const float*)d_in[21];
    const float* bw  = (const float*)d_in[22], *bbv = (const float*)d_in[23];
    const float* tlw0= (const float*)d_in[24], *tlb0= (const float*)d_in[25];
    const float* tlw1= (const float*)d_in[26], *tlb1= (const float*)d_in[27];
    const float* blw = (const float*)d_in[28], *blb = (const float*)d_in[29];
    float* out = (float*)d_out;

    dim3 tb(32, 8);
    k_prep<<<876, tb>>>(xyz, mw0, mw1, mw2, lw0, lw1, lw2);          // 0
    k_sample<<<BP, 128>>>(xyz, bsize, inds);                         // 1
    k_ftrans<<<dim3(625, 8, 8), tb>>>(feat);                         // 2

    int smem_b = (2 * 128 * HST2) * (int)sizeof(float);              // 36864 B
    cudaFuncSetAttribute(k_mlp, cudaFuncAttributeMaxDynamicSharedMemorySize, smem_b);
    k_mlp<<<BP, 128, smem_b>>>(xyz, inds, mb0, mb1, mb2);            // 3 <- profiled

    k_time2<<<BB, 1024>>>(ts, tw0, tb0, tw1, tb1, bw, bbv,
                          tlw0, tlb0, tlw1, tlb1, blw, blb);         // 4
    k_label<<<BP/4, 256>>>(blabel, lb0, lb1, lb2);                   // 5

    const int total = BB*PP*3 + BB*128*PP + BB*256*PP + BB*PP;       // 794624
    k_out<<<(total + 255)/256, 256>>>(out, xyz, inds);               // 6
}